// round 4
// baseline (speedup 1.0000x reference)
#include <cuda_runtime.h>
#include <cstdint>

// ---- detect architecture-specific (sm_103a/sm_100a) compilation pass ----
#ifndef HAS_TC
#  if defined(__CUDA_ARCH_FEAT_SM103_ALL) || defined(__CUDA_ARCH_FEAT_SM100_ALL)
#    define HAS_TC 1
#  endif
#endif
#ifndef HAS_TC
#  ifdef __CUDA_ARCH_HAS_FEATURE__
#    if __CUDA_ARCH_HAS_FEATURE__(SM103_ALL) || __CUDA_ARCH_HAS_FEATURE__(SM100_ALL)
#      define HAS_TC 1
#    endif
#  endif
#endif
#ifndef HAS_TC
#  define HAS_TC 0
#endif

#define NTOK  8192
#define DIM_  2048
#define S_    2048
#define KVH_  8

// ---------------- tile config ----------------
// cg2 path: CTA pair computes 256x256; each CTA loads A[128,K] + B-half[128,K].
// fallback: each CTA computes 128x256 alone.
#define BN 256
#define BK 32                      // floats per K step (128B rows)
#define A_STAGE_BYTES (128 * 128)  // 16 KB

#if HAS_TC
#define STAGES 6
#define PREF 4
#define B_STAGE_BYTES (128 * 128)  // 16 KB (N/2 split)
#else
#define STAGES 4
#define PREF (STAGES - 1)
#define B_STAGE_BYTES (256 * 128)  // 32 KB (full N)
#endif

#define SMEM_AOFF 1024
#define SMEM_BOFF (SMEM_AOFF + STAGES * A_STAGE_BYTES)
// both paths total 197632 B; host always requests this
#define SMEM_REQ 197632

#define TMEM_COLS 256
// cg2 idesc: c=F32, a=TF32, b=TF32, N=256, M=256 (pair-wide)
#define IDESC_CG2 ((1u << 4) | (2u << 7) | (2u << 10) | ((256 / 8) << 17) | ((256 / 16) << 24))

// ---------------- scratch ----------------
__device__ float g_xr  [(size_t)NTOK * DIM_];
__device__ float g_w   [(size_t)(3072 + 2048) * DIM_];
__device__ float g_qkv [(size_t)NTOK * 3072];
__device__ float g_attn[(size_t)NTOK * DIM_];
#define WO_OFF ((size_t)3072 * DIM_)

// ---------------- helpers ----------------
__device__ __forceinline__ uint32_t smem_u32(const void* p) {
    return (uint32_t)__cvta_generic_to_shared(p);
}
__device__ __forceinline__ void cp_async16(uint32_t saddr, const void* gptr) {
    asm volatile("cp.async.cg.shared.global [%0], [%1], 16;\n" :: "r"(saddr), "l"(gptr));
}
__device__ __forceinline__ uint32_t swz128(uint32_t off) {
    return off ^ ((off >> 3) & 0x70);
}
__device__ __forceinline__ float round_tf32f(float f) {
    uint32_t u;
    asm("cvt.rna.tf32.f32 %0, %1;" : "=r"(u) : "f"(f));
    return __uint_as_float(u);
}
__device__ __forceinline__ uint32_t lds32(const char* smem, uint32_t off) {
    return *reinterpret_cast<const uint32_t*>(smem + off);
}
__device__ __forceinline__ void mma_tf32(float c[4], const uint32_t a[4], const uint32_t b[2]) {
    asm volatile(
        "mma.sync.aligned.m16n8k8.row.col.f32.tf32.tf32.f32 "
        "{%0,%1,%2,%3}, {%4,%5,%6,%7}, {%8,%9}, {%0,%1,%2,%3};"
        : "+f"(c[0]), "+f"(c[1]), "+f"(c[2]), "+f"(c[3])
        : "r"(a[0]), "r"(a[1]), "r"(a[2]), "r"(a[3]), "r"(b[0]), "r"(b[1]));
}

#if HAS_TC
#define MBARRIER_INIT(addr, cnt) \
    asm volatile("mbarrier.init.shared.b64 [%0], %1;" :: "r"(addr), "r"(cnt) : "memory")

// local-scope acquire wait (empty/done barriers: commit arrives locally)
#define MBARRIER_WAIT_PARITY(addr, ph) do {                                        \
    uint32_t _m = (addr); uint32_t _p = (ph); uint32_t _d;                         \
    asm volatile("{\n\t.reg .pred p;\n\t"                                          \
        "mbarrier.try_wait.parity.acquire.cta.shared::cta.b64 p, [%1], %2;\n\t"    \
        "selp.b32 %0, 1, 0, p;\n\t}"                                               \
        : "=r"(_d) : "r"(_m), "r"(_p) : "memory");                                 \
    if (!_d) {                                                                     \
        asm volatile("{\n\t.reg .pred P1;\n\t"                                     \
        "WL_%=:\n\t"                                                               \
        "mbarrier.try_wait.parity.acquire.cta.shared::cta.b64 P1, [%0], %1, 0x989680;\n\t" \
        "@P1 bra.uni WD_%=;\n\t"                                                   \
        "bra.uni WL_%=;\n\t"                                                       \
        "WD_%=:\n\t}" :: "r"(_m), "r"(_p) : "memory");                             \
    }                                                                              \
} while (0)

// cluster-scope acquire wait (full barrier: peer CTA's smem writes must be visible)
#define MBARRIER_WAIT_PARITY_CL(addr, ph) do {                                     \
    uint32_t _m = (addr); uint32_t _p = (ph); uint32_t _d;                         \
    asm volatile("{\n\t.reg .pred p;\n\t"                                          \
        "mbarrier.try_wait.parity.acquire.cluster.shared::cta.b64 p, [%1], %2;\n\t" \
        "selp.b32 %0, 1, 0, p;\n\t}"                                               \
        : "=r"(_d) : "r"(_m), "r"(_p) : "memory");                                 \
    if (!_d) {                                                                     \
        asm volatile("{\n\t.reg .pred P1;\n\t"                                     \
        "WL_%=:\n\t"                                                               \
        "mbarrier.try_wait.parity.acquire.cluster.shared::cta.b64 P1, [%0], %1, 0x989680;\n\t" \
        "@P1 bra.uni WD_%=;\n\t"                                                   \
        "bra.uni WL_%=;\n\t"                                                       \
        "WD_%=:\n\t}" :: "r"(_m), "r"(_p) : "memory");                             \
    }                                                                              \
} while (0)

// arrive (release, cluster) on the barrier at this smem offset in cluster CTA `rank`
#define MBARRIER_ARRIVE_CLUSTER(local_addr, rank) \
    asm volatile("{\n\t.reg .b32 remAddr;\n\t" \
        "mapa.shared::cluster.u32 remAddr, %0, %1;\n\t" \
        "mbarrier.arrive.release.cluster.shared::cluster.b64 _, [remAddr];\n\t}" \
        :: "r"((uint32_t)(local_addr)), "r"((uint32_t)(rank)) : "memory")

#define TCGEN05_ALLOC_CG2(saddr, ncols) \
    asm volatile("tcgen05.alloc.cta_group::2.sync.aligned.shared::cta.b32 [%0], %1;" \
                 :: "r"((uint32_t)(saddr)), "r"((uint32_t)(ncols)) : "memory")
#define TCGEN05_RELINQ_CG2() \
    asm volatile("tcgen05.relinquish_alloc_permit.cta_group::2.sync.aligned;")
#define TCGEN05_DEALLOC_CG2(tmem, ncols) \
    asm volatile("tcgen05.dealloc.cta_group::2.sync.aligned.b32 %0, %1;" \
                 :: "r"(tmem), "r"((uint32_t)(ncols)))
#define TCGEN05_COMMIT_MC_CG2(mbar, mask) \
    asm volatile("tcgen05.commit.cta_group::2.mbarrier::arrive::one.shared::cluster.multicast::cluster.b64 [%0], %1;" \
                 :: "r"((uint32_t)(mbar)), "h"((uint16_t)(mask)) : "memory")
#define TCGEN05_FENCE_AFTER()  asm volatile("tcgen05.fence::after_thread_sync;" ::: "memory")
#define TCGEN05_FENCE_BEFORE() asm volatile("tcgen05.fence::before_thread_sync;" ::: "memory")
#define TCGEN05_WAIT_LD()      asm volatile("tcgen05.wait::ld.sync.aligned;" ::: "memory")
#define FENCE_PROXY_ASYNC()    asm volatile("fence.proxy.async.shared::cta;" ::: "memory")
#define CLUSTER_SYNC() do { \
    asm volatile("barrier.cluster.arrive.aligned;" ::: "memory"); \
    asm volatile("barrier.cluster.wait.aligned;" ::: "memory"); \
} while (0)

#define TCGEN05_LD_X32(r, taddr) \
    asm volatile("tcgen05.ld.sync.aligned.32x32b.x32.b32 " \
        "{%0, %1, %2, %3, %4, %5, %6, %7, %8, %9, %10, %11, %12, %13, %14, %15, " \
        " %16, %17, %18, %19, %20, %21, %22, %23, %24, %25, %26, %27, %28, %29, %30, %31}, [%32];" \
        : "=r"((r)[0]), "=r"((r)[1]), "=r"((r)[2]), "=r"((r)[3]),      \
          "=r"((r)[4]), "=r"((r)[5]), "=r"((r)[6]), "=r"((r)[7]),      \
          "=r"((r)[8]), "=r"((r)[9]), "=r"((r)[10]), "=r"((r)[11]),    \
          "=r"((r)[12]), "=r"((r)[13]), "=r"((r)[14]), "=r"((r)[15]),  \
          "=r"((r)[16]), "=r"((r)[17]), "=r"((r)[18]), "=r"((r)[19]),  \
          "=r"((r)[20]), "=r"((r)[21]), "=r"((r)[22]), "=r"((r)[23]),  \
          "=r"((r)[24]), "=r"((r)[25]), "=r"((r)[26]), "=r"((r)[27]),  \
          "=r"((r)[28]), "=r"((r)[29]), "=r"((r)[30]), "=r"((r)[31])   \
        : "r"(taddr))

static constexpr uint64_t SMEM_DESC_BASE_SW128 =
    (uint64_t(2) << 61) | (uint64_t(1) << 46) | (uint64_t(64) << 32) | (uint64_t(1) << 16);
#define MAKE_SMEM_DESC(addr) (SMEM_DESC_BASE_SW128 | ((uint64_t)((addr) >> 4) & 0x3FFF))

__device__ __forceinline__ void mma_tf32_ss_cg2(uint32_t d_tmem, uint64_t a_desc,
                                                uint64_t b_desc, uint32_t idesc, bool acc) {
    uint32_t en = acc ? 1u : 0u;
    asm volatile(
        "{\n\t.reg .pred p;\n\t"
        "setp.ne.u32 p, %4, 0;\n\t"
        "tcgen05.mma.cta_group::2.kind::tf32 [%0], %1, %2, %3, "
        "{%5, %5, %5, %5, %5, %5, %5, %5}, p;\n\t}"
        :: "r"(d_tmem), "l"(a_desc), "l"(b_desc), "r"(idesc), "r"(en), "r"(0u)
        : "memory");
}
#endif  // HAS_TC

// ---------------- tf32 pre-rounding ----------------
__global__ void round_k(const float4* __restrict__ in, float4* __restrict__ out, int n4) {
    int i = blockIdx.x * blockDim.x + threadIdx.x;
    if (i < n4) {
        float4 v = in[i];
        v.x = round_tf32f(v.x); v.y = round_tf32f(v.y);
        v.z = round_tf32f(v.z); v.w = round_tf32f(v.w);
        out[i] = v;
    }
}

// ---------------- GEMM: C[M,ldc] = A[M,K] * B[N,K]^T ----------------
// grid = (2, N/256, M/256), block = 256. cluster (2,1,1): CTA pair shares an
// M-256 x N-256 tile; rank r owns A rows [pair*256 + r*128, +128) and B rows
// [bn + r*128, +128). Operands must be tf32-pre-rounded.
__global__ void __launch_bounds__(256, 1) __cluster_dims__(2, 1, 1)
gemm_tc(const float* __restrict__ A, const float* __restrict__ Bm,
        float* __restrict__ C, int K, int ldc) {
    extern __shared__ char smem[];
    const uint32_t sbase = smem_u32(smem);
    const int tid = threadIdx.x;
    const int wid = tid >> 5, lid = tid & 31;
    const int rank = blockIdx.x & 1;
    const int bmp = blockIdx.z * 256;            // pair M base
    const int bn  = blockIdx.y * 256;
    const int KT = K / BK;

    // cooperative stage loader: 256 threads, 16B each, SW128 layout
    const int r0 = tid >> 3;            // 0..31
    const int cb = (tid & 7) * 16;      // byte col within 128B row

#if HAS_TC
    const float* Abase = A  + (size_t)(bmp + rank * 128) * K;
    const float* Bbase = Bm + (size_t)(bn  + rank * 128) * K;
    auto issue_loads = [&](int j) {
        const int s = j % STAGES;
        const float* Ag = Abase + (size_t)j * BK;
        const float* Bg = Bbase + (size_t)j * BK;
        const uint32_t as = sbase + SMEM_AOFF + s * A_STAGE_BYTES;
        const uint32_t bs = sbase + SMEM_BOFF + s * B_STAGE_BYTES;
        #pragma unroll
        for (int r = 0; r < 128; r += 32) {
            int row = r + r0;
            cp_async16(as + swz128(row * 128 + cb), Ag + (size_t)row * K + (cb >> 2));
            cp_async16(bs + swz128(row * 128 + cb), Bg + (size_t)row * K + (cb >> 2));
        }
    };

    const uint32_t EMPTY_BAR = sbase + 16;                      // STAGES bars
    const uint32_t FULL_BAR  = sbase + 16 + STAGES * 8;         // STAGES bars (used on rank0)
    const uint32_t DONE_BAR  = sbase + 16 + 2 * STAGES * 8;

    if (wid == 0) TCGEN05_ALLOC_CG2(sbase, TMEM_COLS);
    if (tid == 0) {
        #pragma unroll
        for (int s = 0; s < STAGES; s++) {
            MBARRIER_INIT(EMPTY_BAR + s * 8, 1);   // multicast commit: 1 arrival/CTA
            MBARRIER_INIT(FULL_BAR + s * 8, 2);    // both CTAs arrive
        }
        MBARRIER_INIT(DONE_BAR, 1);
    }
    __syncthreads();
    CLUSTER_SYNC();   // barriers + TMEM alloc visible cluster-wide

    uint32_t tmem;
    asm volatile("ld.shared.b32 %0, [%1];" : "=r"(tmem) : "r"(sbase));

    #pragma unroll
    for (int j = 0; j < PREF; j++) {
        issue_loads(j);
        asm volatile("cp.async.commit_group;\n" ::);
    }

    for (int kt = 0; kt < KT; kt++) {
        const int j = kt + PREF;
        if (j < KT) {
            if (j >= STAGES) {
                int ph = ((j / STAGES) - 1) & 1;
                MBARRIER_WAIT_PARITY(EMPTY_BAR + (j % STAGES) * 8, ph);
            }
            issue_loads(j);
        }
        asm volatile("cp.async.commit_group;\n" ::);
        asm volatile("cp.async.wait_group %0;\n" :: "n"(PREF));
        FENCE_PROXY_ASYNC();
        __syncthreads();

        const int s = kt % STAGES;
        if (tid == 0) MBARRIER_ARRIVE_CLUSTER(FULL_BAR + s * 8, 0);

        if (rank == 0 && tid == 0) {
            MBARRIER_WAIT_PARITY_CL(FULL_BAR + s * 8, (kt / STAGES) & 1);
            uint64_t ad = MAKE_SMEM_DESC(sbase + SMEM_AOFF + s * A_STAGE_BYTES);
            uint64_t bd = MAKE_SMEM_DESC(sbase + SMEM_BOFF + s * B_STAGE_BYTES);
            #pragma unroll
            for (int k = 0; k < 4; k++)
                mma_tf32_ss_cg2(tmem, ad + k * 2, bd + k * 2, IDESC_CG2,
                                (kt > 0) || (k > 0));
            TCGEN05_COMMIT_MC_CG2(EMPTY_BAR + s * 8, 0x3);
        }
    }

    if (rank == 0 && tid == 0) TCGEN05_COMMIT_MC_CG2(DONE_BAR, 0x3);
    MBARRIER_WAIT_PARITY(DONE_BAR, 0);
    TCGEN05_FENCE_AFTER();

    // epilogue: this CTA owns D rows [bmp + rank*128, +128), cols [bn, bn+256)
    {
        const int row = bmp + rank * 128 + (wid & 3) * 32 + lid;
        const int cbase = (wid >> 2) * 128;
        float* crow = C + (size_t)row * ldc + bn + cbase;
        #pragma unroll
        for (int c2 = 0; c2 < 128; c2 += 32) {
            uint32_t r[32];
            TCGEN05_LD_X32(r, tmem + cbase + c2);
            TCGEN05_WAIT_LD();
            #pragma unroll
            for (int q = 0; q < 32; q += 4) {
                float4 v = make_float4(__uint_as_float(r[q]), __uint_as_float(r[q + 1]),
                                       __uint_as_float(r[q + 2]), __uint_as_float(r[q + 3]));
                *reinterpret_cast<float4*>(crow + c2 + q) = v;
            }
        }
    }
    TCGEN05_FENCE_BEFORE();
    __syncthreads();
    if (wid == 0) {
        TCGEN05_RELINQ_CG2();
        TCGEN05_DEALLOC_CG2(tmem, TMEM_COLS);
    }
    CLUSTER_SYNC();

#else
    // ======== legacy mma.sync fallback: 128x256 per CTA ========
    const int bm = bmp + rank * 128;
    auto issue_loads = [&](int j) {
        const int s = j & (STAGES - 1);
        const float* Ag = A  + (size_t)bm * K + (size_t)j * BK;
        const float* Bg = Bm + (size_t)bn * K + (size_t)j * BK;
        const uint32_t as = sbase + SMEM_AOFF + s * A_STAGE_BYTES;
        const uint32_t bs = sbase + SMEM_BOFF + s * B_STAGE_BYTES;
        #pragma unroll
        for (int r = 0; r < 128; r += 32) {
            int row = r + r0;
            cp_async16(as + swz128(row * 128 + cb), Ag + (size_t)row * K + (cb >> 2));
        }
        #pragma unroll
        for (int r = 0; r < 256; r += 32) {
            int row = r + r0;
            cp_async16(bs + swz128(row * 128 + cb), Bg + (size_t)row * K + (cb >> 2));
        }
    };

    const int wr = wid >> 2, wc = wid & 3;
    const int grp = lid >> 2, tig = lid & 3;

    float acc[4][8][4];
    #pragma unroll
    for (int i = 0; i < 4; i++)
        #pragma unroll
        for (int j = 0; j < 8; j++)
            #pragma unroll
            for (int r = 0; r < 4; r++) acc[i][j][r] = 0.f;

    auto compute = [&](int s) {
        const char* as = smem + SMEM_AOFF + s * A_STAGE_BYTES;
        const char* bs = smem + SMEM_BOFF + s * B_STAGE_BYTES;
        #pragma unroll
        for (int kk = 0; kk < BK; kk += 8) {
            uint32_t af[4][4], bf[8][2];
            #pragma unroll
            for (int mt = 0; mt < 4; mt++) {
                int rb = wr * 64 + mt * 16;
                af[mt][0] = lds32(as, swz128((rb + grp)     * 128 + (kk + tig) * 4));
                af[mt][1] = lds32(as, swz128((rb + grp + 8) * 128 + (kk + tig) * 4));
                af[mt][2] = lds32(as, swz128((rb + grp)     * 128 + (kk + tig + 4) * 4));
                af[mt][3] = lds32(as, swz128((rb + grp + 8) * 128 + (kk + tig + 4) * 4));
            }
            #pragma unroll
            for (int nt = 0; nt < 8; nt++) {
                int cbn = wc * 64 + nt * 8;
                bf[nt][0] = lds32(bs, swz128((cbn + grp) * 128 + (kk + tig) * 4));
                bf[nt][1] = lds32(bs, swz128((cbn + grp) * 128 + (kk + tig + 4) * 4));
            }
            #pragma unroll
            for (int mt = 0; mt < 4; mt++)
                #pragma unroll
                for (int nt = 0; nt < 8; nt++)
                    mma_tf32(acc[mt][nt], af[mt], bf[nt]);
        }
    };

    #pragma unroll
    for (int j = 0; j < STAGES - 1; j++) {
        issue_loads(j);
        asm volatile("cp.async.commit_group;\n" ::);
    }
    asm volatile("cp.async.wait_group %0;\n" :: "n"(STAGES - 2));
    __syncthreads();

    for (int kt = 0; kt < KT; kt++) {
        int j = kt + STAGES - 1;
        if (j < KT) issue_loads(j);
        asm volatile("cp.async.commit_group;\n" ::);
        compute(kt & (STAGES - 1));
        asm volatile("cp.async.wait_group %0;\n" :: "n"(STAGES - 2));
        __syncthreads();
    }

    #pragma unroll
    for (int mt = 0; mt < 4; mt++) {
        #pragma unroll
        for (int nt = 0; nt < 8; nt++) {
            int row = bm + wr * 64 + mt * 16 + grp;
            int col = bn + wc * 64 + nt * 8 + tig * 2;
            *reinterpret_cast<float2*>(C + (size_t)row * ldc + col) =
                make_float2(acc[mt][nt][0], acc[mt][nt][1]);
            *reinterpret_cast<float2*>(C + (size_t)(row + 8) * ldc + col) =
                make_float2(acc[mt][nt][2], acc[mt][nt][3]);
        }
    }
#endif
}

// ---------------- per-token attention (RoPE + 8-way softmax) ----------------
__global__ void attn_kernel(const float* __restrict__ qkv,
                            const float* __restrict__ cos_g,
                            const float* __restrict__ sin_g,
                            float* __restrict__ attn_out) {
    const int t = blockIdx.x;
    const int s = t & (S_ - 1);
    const float* base = qkv + (size_t)t * 3072;

    __shared__ float2 ks2[KVH_][32];
    __shared__ float2 vs2[KVH_][32];

    const int tid = threadIdx.x;
    const int j = tid >> 5, i = tid & 31;

    {
        float2 kv = reinterpret_cast<const float2*>(base + 2048 + j * 64)[i];
        float c = cos_g[s * 32 + i], sn = sin_g[s * 32 + i];
        ks2[j][i] = make_float2(kv.x * c - kv.y * sn, kv.x * sn + kv.y * c);
        vs2[j][i] = reinterpret_cast<const float2*>(base + 2560 + j * 64)[i];
    }
    __syncthreads();

    const int warp = tid >> 5, lane = tid & 31;
    const float cc  = cos_g[s * 32 + lane];
    const float ssn = sin_g[s * 32 + lane];

    #pragma unroll
    for (int hh = 0; hh < 4; hh++) {
        int h = warp * 4 + hh;
        float2 q = reinterpret_cast<const float2*>(base + h * 64)[lane];
        float qr = q.x * cc - q.y * ssn;
        float qi = q.x * ssn + q.y * cc;

        float sc[KVH_];
        #pragma unroll
        for (int jj = 0; jj < KVH_; jj++) {
            float2 k2 = ks2[jj][lane];
            float p = qr * k2.x + qi * k2.y;
            p += __shfl_xor_sync(0xffffffffu, p, 16);
            p += __shfl_xor_sync(0xffffffffu, p, 8);
            p += __shfl_xor_sync(0xffffffffu, p, 4);
            p += __shfl_xor_sync(0xffffffffu, p, 2);
            p += __shfl_xor_sync(0xffffffffu, p, 1);
            sc[jj] = p * 0.125f;
        }
        float m = sc[0];
        #pragma unroll
        for (int jj = 1; jj < KVH_; jj++) m = fmaxf(m, sc[jj]);
        float sum = 0.f;
        #pragma unroll
        for (int jj = 0; jj < KVH_; jj++) { sc[jj] = __expf(sc[jj] - m); sum += sc[jj]; }
        float inv = 1.f / sum;
        float o0 = 0.f, o1 = 0.f;
        #pragma unroll
        for (int jj = 0; jj < KVH_; jj++) {
            float w = sc[jj] * inv;
            float2 v2 = vs2[jj][lane];
            o0 += w * v2.x;
            o1 += w * v2.y;
        }
        reinterpret_cast<float2*>(attn_out + (size_t)t * 2048 + h * 64)[lane] =
            make_float2(round_tf32f(o0), round_tf32f(o1));
    }
}

// ---------------- launch ----------------
extern "C" void kernel_launch(void* const* d_in, const int* in_sizes, int n_in,
                              void* d_out, int out_size) {
    const float* x  = (const float*)d_in[0];
    const float* wq = (const float*)d_in[1];
    const float* wk = (const float*)d_in[2];
    const float* wv = (const float*)d_in[3];
    const float* wo = (const float*)d_in[4];
    const float* fc = (const float*)d_in[5];
    const float* fs = (const float*)d_in[6];
    float* out = (float*)d_out;

    float *xr, *w, *qkv, *attn;
    cudaGetSymbolAddress((void**)&xr,   g_xr);
    cudaGetSymbolAddress((void**)&w,    g_w);
    cudaGetSymbolAddress((void**)&qkv,  g_qkv);
    cudaGetSymbolAddress((void**)&attn, g_attn);

    cudaFuncSetAttribute(gemm_tc, cudaFuncAttributeMaxDynamicSharedMemorySize, SMEM_REQ);

    auto launch_round = [](const float* src, float* dst, size_t n) {
        int n4 = (int)(n / 4);
        round_k<<<(n4 + 255) / 256, 256>>>((const float4*)src, (float4*)dst, n4);
    };
    launch_round(x,  xr,                       (size_t)NTOK * DIM_);
    launch_round(wq, w,                        (size_t)2048 * DIM_);
    launch_round(wk, w + (size_t)2048 * DIM_,  (size_t)512 * DIM_);
    launch_round(wv, w + (size_t)2560 * DIM_,  (size_t)512 * DIM_);
    launch_round(wo, w + WO_OFF,               (size_t)2048 * DIM_);

    // fused QKV projection: [8192,2048] x [3072,2048]^T -> [8192,3072]
    gemm_tc<<<dim3(2, 3072 / 256, NTOK / 256), 256, SMEM_REQ>>>(xr, w, qkv, DIM_, 3072);

    // RoPE + per-token attention (tf32-rounded output)
    attn_kernel<<<NTOK, 256>>>(qkv, fc, fs, attn);

    // output projection: [8192,2048] x [2048,2048]^T -> [8192,2048]
    gemm_tc<<<dim3(2, DIM_ / 256, NTOK / 256), 256, SMEM_REQ>>>(attn, w + WO_OFF, out, DIM_, DIM_);
}

// round 5
// speedup vs baseline: 1.9772x; 1.9772x over previous
#include <cuda_runtime.h>
#include <cstdint>

// ---- detect architecture-specific (sm_103a/sm_100a) compilation pass ----
#ifndef HAS_TC
#  if defined(__CUDA_ARCH_FEAT_SM103_ALL) || defined(__CUDA_ARCH_FEAT_SM100_ALL)
#    define HAS_TC 1
#  endif
#endif
#ifndef HAS_TC
#  ifdef __CUDA_ARCH_HAS_FEATURE__
#    if __CUDA_ARCH_HAS_FEATURE__(SM103_ALL) || __CUDA_ARCH_HAS_FEATURE__(SM100_ALL)
#      define HAS_TC 1
#    endif
#  endif
#endif
#ifndef HAS_TC
#  define HAS_TC 0
#endif

#define NTOK  8192
#define DIM_  2048
#define S_    2048
#define KVH_  8

// ---------------- tile config ----------------
// tcgen05 path: one CTA computes 256x256 via two M=128 MMAs sharing B.
// Stage layout (64 KB): [A0 16KB | A1 16KB | B 32KB] x 3 stages.
#define BK 32                      // floats per K step (128B rows)
#define STAGES 3
#define PREF 2
#define STAGE_BYTES 65536
#define A0_OFF 0
#define A1_OFF 16384
#define B_OFF  32768

#define SMEM_AOFF 1024
#define SMEM_REQ  (1024 + STAGES * STAGE_BYTES)   // 197632

#define TMEM_COLS 512
// cg1 idesc: c=F32, a=TF32, b=TF32, M=128, N=256, K-major both
#define IDESC ((1u << 4) | (2u << 7) | (2u << 10) | ((256 / 8) << 17) | ((128 / 16) << 24))

// ---------------- scratch ----------------
__device__ float g_xr  [(size_t)NTOK * DIM_];
__device__ float g_w   [(size_t)(3072 + 2048) * DIM_];
__device__ float g_qkv [(size_t)NTOK * 3072];
__device__ float g_attn[(size_t)NTOK * DIM_];
#define WO_OFF ((size_t)3072 * DIM_)

// ---------------- helpers ----------------
__device__ __forceinline__ uint32_t smem_u32(const void* p) {
    return (uint32_t)__cvta_generic_to_shared(p);
}
__device__ __forceinline__ void cp_async16(uint32_t saddr, const void* gptr) {
    asm volatile("cp.async.cg.shared.global [%0], [%1], 16;\n" :: "r"(saddr), "l"(gptr));
}
__device__ __forceinline__ uint32_t swz128(uint32_t off) {
    return off ^ ((off >> 3) & 0x70);
}
__device__ __forceinline__ float round_tf32f(float f) {
    uint32_t u;
    asm("cvt.rna.tf32.f32 %0, %1;" : "=r"(u) : "f"(f));
    return __uint_as_float(u);
}
__device__ __forceinline__ uint32_t lds32(const char* smem, uint32_t off) {
    return *reinterpret_cast<const uint32_t*>(smem + off);
}
__device__ __forceinline__ void mma_tf32(float c[4], const uint32_t a[4], const uint32_t b[2]) {
    asm volatile(
        "mma.sync.aligned.m16n8k8.row.col.f32.tf32.tf32.f32 "
        "{%0,%1,%2,%3}, {%4,%5,%6,%7}, {%8,%9}, {%0,%1,%2,%3};"
        : "+f"(c[0]), "+f"(c[1]), "+f"(c[2]), "+f"(c[3])
        : "r"(a[0]), "r"(a[1]), "r"(a[2]), "r"(a[3]), "r"(b[0]), "r"(b[1]));
}

#if HAS_TC
#define MBARRIER_INIT(addr, cnt) \
    asm volatile("mbarrier.init.shared.b64 [%0], %1;" :: "r"(addr), "r"(cnt) : "memory")

#define MBARRIER_WAIT_PARITY(addr, ph) do {                                        \
    uint32_t _m = (addr); uint32_t _p = (ph); uint32_t _d;                         \
    asm volatile("{\n\t.reg .pred p;\n\t"                                          \
        "mbarrier.try_wait.parity.acquire.cta.shared::cta.b64 p, [%1], %2;\n\t"    \
        "selp.b32 %0, 1, 0, p;\n\t}"                                               \
        : "=r"(_d) : "r"(_m), "r"(_p) : "memory");                                 \
    if (!_d) {                                                                     \
        asm volatile("{\n\t.reg .pred P1;\n\t"                                     \
        "WL_%=:\n\t"                                                               \
        "mbarrier.try_wait.parity.acquire.cta.shared::cta.b64 P1, [%0], %1, 0x989680;\n\t" \
        "@P1 bra.uni WD_%=;\n\t"                                                   \
        "bra.uni WL_%=;\n\t"                                                       \
        "WD_%=:\n\t}" :: "r"(_m), "r"(_p) : "memory");                             \
    }                                                                              \
} while (0)

#define TCGEN05_ALLOC(saddr, ncols) \
    asm volatile("tcgen05.alloc.cta_group::1.sync.aligned.shared::cta.b32 [%0], %1;" \
                 :: "r"((uint32_t)(saddr)), "r"((uint32_t)(ncols)) : "memory")
#define TCGEN05_RELINQ() \
    asm volatile("tcgen05.relinquish_alloc_permit.cta_group::1.sync.aligned;")
#define TCGEN05_DEALLOC(tmem, ncols) \
    asm volatile("tcgen05.dealloc.cta_group::1.sync.aligned.b32 %0, %1;" \
                 :: "r"(tmem), "r"((uint32_t)(ncols)))
#define TCGEN05_COMMIT(mbar) \
    asm volatile("tcgen05.commit.cta_group::1.mbarrier::arrive::one.shared::cluster.b64 [%0];" \
                 :: "r"((uint32_t)(mbar)) : "memory")
#define TCGEN05_FENCE_AFTER()  asm volatile("tcgen05.fence::after_thread_sync;" ::: "memory")
#define TCGEN05_FENCE_BEFORE() asm volatile("tcgen05.fence::before_thread_sync;" ::: "memory")
#define TCGEN05_WAIT_LD()      asm volatile("tcgen05.wait::ld.sync.aligned;" ::: "memory")
#define FENCE_PROXY_ASYNC()    asm volatile("fence.proxy.async.shared::cta;" ::: "memory")

#define TCGEN05_LD_X32(r, taddr) \
    asm volatile("tcgen05.ld.sync.aligned.32x32b.x32.b32 " \
        "{%0, %1, %2, %3, %4, %5, %6, %7, %8, %9, %10, %11, %12, %13, %14, %15, " \
        " %16, %17, %18, %19, %20, %21, %22, %23, %24, %25, %26, %27, %28, %29, %30, %31}, [%32];" \
        : "=r"((r)[0]), "=r"((r)[1]), "=r"((r)[2]), "=r"((r)[3]),      \
          "=r"((r)[4]), "=r"((r)[5]), "=r"((r)[6]), "=r"((r)[7]),      \
          "=r"((r)[8]), "=r"((r)[9]), "=r"((r)[10]), "=r"((r)[11]),    \
          "=r"((r)[12]), "=r"((r)[13]), "=r"((r)[14]), "=r"((r)[15]),  \
          "=r"((r)[16]), "=r"((r)[17]), "=r"((r)[18]), "=r"((r)[19]),  \
          "=r"((r)[20]), "=r"((r)[21]), "=r"((r)[22]), "=r"((r)[23]),  \
          "=r"((r)[24]), "=r"((r)[25]), "=r"((r)[26]), "=r"((r)[27]),  \
          "=r"((r)[28]), "=r"((r)[29]), "=r"((r)[30]), "=r"((r)[31])   \
        : "r"(taddr))

static constexpr uint64_t SMEM_DESC_BASE_SW128 =
    (uint64_t(2) << 61) | (uint64_t(1) << 46) | (uint64_t(64) << 32) | (uint64_t(1) << 16);
#define MAKE_SMEM_DESC(addr) (SMEM_DESC_BASE_SW128 | ((uint64_t)((addr) >> 4) & 0x3FFF))

__device__ __forceinline__ void mma_tf32_ss(uint32_t d_tmem, uint64_t a_desc,
                                            uint64_t b_desc, uint32_t idesc, bool acc) {
    uint32_t en = acc ? 1u : 0u;
    asm volatile(
        "{\n\t.reg .pred p;\n\t"
        "setp.ne.u32 p, %4, 0;\n\t"
        "tcgen05.mma.cta_group::1.kind::tf32 [%0], %1, %2, %3, {%5, %5, %5, %5}, p;\n\t}"
        :: "r"(d_tmem), "l"(a_desc), "l"(b_desc), "r"(idesc), "r"(en), "r"(0u)
        : "memory");
}
#endif  // HAS_TC

// ---------------- tf32 pre-rounding ----------------
__global__ void round_k(const float4* __restrict__ in, float4* __restrict__ out, int n4) {
    int i = blockIdx.x * blockDim.x + threadIdx.x;
    if (i < n4) {
        float4 v = in[i];
        v.x = round_tf32f(v.x); v.y = round_tf32f(v.y);
        v.z = round_tf32f(v.z); v.w = round_tf32f(v.w);
        out[i] = v;
    }
}

// ---------------- GEMM: C[M,ldc] = A[M,K] * B[N,K]^T ----------------
// grid = (N/256, M/256), block = 256. Operands must be tf32-pre-rounded.
// tcgen05 path: 256x256 tile = two M=128 MMA dispatches sharing one B operand.
__global__ void __launch_bounds__(256, 1)
gemm_tc(const float* __restrict__ A, const float* __restrict__ Bm,
        float* __restrict__ C, int K, int ldc) {
    extern __shared__ char smem[];
    const uint32_t sbase = smem_u32(smem);
    const int tid = threadIdx.x;
    const int wid = tid >> 5, lid = tid & 31;
    const int bmp = blockIdx.y * 256;
    const int bn  = blockIdx.x * 256;
    const int KT = K / BK;

    const int r0 = tid >> 3;            // 0..31
    const int cb = (tid & 7) * 16;      // byte col within 128B row

#if HAS_TC
    // ======== tcgen05 path ========
    const float* A0g = A  + (size_t)bmp * K;
    const float* A1g = A  + (size_t)(bmp + 128) * K;
    const float* Bg0 = Bm + (size_t)bn * K;

    auto issue_loads = [&](int j) {
        const int s = j % STAGES;
        const uint32_t st = sbase + SMEM_AOFF + s * STAGE_BYTES;
        const size_t kof = (size_t)j * BK + (cb >> 2);
        #pragma unroll
        for (int r = 0; r < 128; r += 32) {
            int row = r + r0;
            uint32_t so = swz128(row * 128 + cb);
            cp_async16(st + A0_OFF + so, A0g + (size_t)row * K + kof);
            cp_async16(st + A1_OFF + so, A1g + (size_t)row * K + kof);
        }
        #pragma unroll
        for (int r = 0; r < 256; r += 32) {
            int row = r + r0;
            cp_async16(st + B_OFF + swz128(row * 128 + cb), Bg0 + (size_t)row * K + kof);
        }
    };

    const uint32_t EMPTY_BAR = sbase + 16;       // STAGES bars
    const uint32_t DONE_BAR  = sbase + 16 + STAGES * 8;

    if (wid == 0) TCGEN05_ALLOC(sbase, TMEM_COLS);
    if (tid == 0) {
        #pragma unroll
        for (int s = 0; s < STAGES; s++) MBARRIER_INIT(EMPTY_BAR + s * 8, 1);
        MBARRIER_INIT(DONE_BAR, 1);
    }
    __syncthreads();
    if (wid == 0) TCGEN05_RELINQ();

    uint32_t tmem;
    asm volatile("ld.shared.b32 %0, [%1];" : "=r"(tmem) : "r"(sbase));
    const uint32_t D0 = tmem, D1 = tmem + 256;

    #pragma unroll
    for (int j = 0; j < PREF; j++) {
        issue_loads(j);
        asm volatile("cp.async.commit_group;\n" ::);
    }

    for (int kt = 0; kt < KT; kt++) {
        const int j = kt + PREF;
        if (j < KT) {
            if (j >= STAGES) {
                int ph = ((j / STAGES) - 1) & 1;
                MBARRIER_WAIT_PARITY(EMPTY_BAR + (j % STAGES) * 8, ph);
            }
            issue_loads(j);
        }
        asm volatile("cp.async.commit_group;\n" ::);
        asm volatile("cp.async.wait_group %0;\n" :: "n"(PREF));
        FENCE_PROXY_ASYNC();
        __syncthreads();

        if (tid == 0) {
            const int s = kt % STAGES;
            const uint32_t st = sbase + SMEM_AOFF + s * STAGE_BYTES;
            uint64_t a0 = MAKE_SMEM_DESC(st + A0_OFF);
            uint64_t a1 = MAKE_SMEM_DESC(st + A1_OFF);
            uint64_t bd = MAKE_SMEM_DESC(st + B_OFF);
            bool acc0 = (kt > 0);
            #pragma unroll
            for (int k = 0; k < 4; k++) {
                mma_tf32_ss(D0, a0 + k * 2, bd + k * 2, IDESC, acc0 || (k > 0));
                mma_tf32_ss(D1, a1 + k * 2, bd + k * 2, IDESC, acc0 || (k > 0));
            }
            TCGEN05_COMMIT(EMPTY_BAR + s * 8);
        }
    }

    if (tid == 0) TCGEN05_COMMIT(DONE_BAR);
    MBARRIER_WAIT_PARITY(DONE_BAR, 0);
    TCGEN05_FENCE_AFTER();

    // epilogue: warps 0-3 -> D0 (rows bmp+0..127), warps 4-7 -> D1 (rows +128)
    {
        const int row = bmp + (wid >> 2) * 128 + (wid & 3) * 32 + lid;
        const uint32_t dT = (wid >> 2) ? D1 : D0;
        float* crow = C + (size_t)row * ldc + bn;
        #pragma unroll
        for (int c2 = 0; c2 < 256; c2 += 32) {
            uint32_t r[32];
            TCGEN05_LD_X32(r, dT + c2);
            TCGEN05_WAIT_LD();
            #pragma unroll
            for (int q = 0; q < 32; q += 4) {
                float4 v = make_float4(__uint_as_float(r[q]), __uint_as_float(r[q + 1]),
                                       __uint_as_float(r[q + 2]), __uint_as_float(r[q + 3]));
                *reinterpret_cast<float4*>(crow + c2 + q) = v;
            }
        }
    }
    TCGEN05_FENCE_BEFORE();
    __syncthreads();
    if (wid == 0) TCGEN05_DEALLOC(tmem, TMEM_COLS);

#else
    // ======== legacy mma.sync fallback: 256x256 tile in two sequential halves ========
    const int wr = wid >> 2, wc = wid & 3;
    const int grp = lid >> 2, tig = lid & 3;

    for (int half = 0; half < 2; half++) {
        const int bm = bmp + half * 128;

        auto issue_loads = [&](int j) {
            const int s = j % STAGES;
            const uint32_t st = sbase + SMEM_AOFF + s * STAGE_BYTES;
            const float* Ag = A  + (size_t)bm * K + (size_t)j * BK;
            const float* Bg = Bm + (size_t)bn * K + (size_t)j * BK;
            #pragma unroll
            for (int r = 0; r < 128; r += 32) {
                int row = r + r0;
                cp_async16(st + A0_OFF + swz128(row * 128 + cb), Ag + (size_t)row * K + (cb >> 2));
            }
            #pragma unroll
            for (int r = 0; r < 256; r += 32) {
                int row = r + r0;
                cp_async16(st + B_OFF + swz128(row * 128 + cb), Bg + (size_t)row * K + (cb >> 2));
            }
        };

        float acc[4][8][4];
        #pragma unroll
        for (int i = 0; i < 4; i++)
            #pragma unroll
            for (int j2 = 0; j2 < 8; j2++)
                #pragma unroll
                for (int r = 0; r < 4; r++) acc[i][j2][r] = 0.f;

        auto compute = [&](int s) {
            const char* st = smem + SMEM_AOFF + s * STAGE_BYTES;
            const char* as = st + A0_OFF;
            const char* bs = st + B_OFF;
            #pragma unroll
            for (int kk = 0; kk < BK; kk += 8) {
                uint32_t af[4][4], bf[8][2];
                #pragma unroll
                for (int mt = 0; mt < 4; mt++) {
                    int rb = wr * 64 + mt * 16;
                    af[mt][0] = lds32(as, swz128((rb + grp)     * 128 + (kk + tig) * 4));
                    af[mt][1] = lds32(as, swz128((rb + grp + 8) * 128 + (kk + tig) * 4));
                    af[mt][2] = lds32(as, swz128((rb + grp)     * 128 + (kk + tig + 4) * 4));
                    af[mt][3] = lds32(as, swz128((rb + grp + 8) * 128 + (kk + tig + 4) * 4));
                }
                #pragma unroll
                for (int nt = 0; nt < 8; nt++) {
                    int cbn = wc * 64 + nt * 8;
                    bf[nt][0] = lds32(bs, swz128((cbn + grp) * 128 + (kk + tig) * 4));
                    bf[nt][1] = lds32(bs, swz128((cbn + grp) * 128 + (kk + tig + 4) * 4));
                }
                #pragma unroll
                for (int mt = 0; mt < 4; mt++)
                    #pragma unroll
                    for (int nt = 0; nt < 8; nt++)
                        mma_tf32(acc[mt][nt], af[mt], bf[nt]);
            }
        };

        #pragma unroll
        for (int j = 0; j < STAGES - 1; j++) {
            issue_loads(j);
            asm volatile("cp.async.commit_group;\n" ::);
        }
        asm volatile("cp.async.wait_group %0;\n" :: "n"(STAGES - 2));
        __syncthreads();

        for (int kt = 0; kt < KT; kt++) {
            int j = kt + STAGES - 1;
            if (j < KT) issue_loads(j);
            asm volatile("cp.async.commit_group;\n" ::);
            compute(kt % STAGES);
            asm volatile("cp.async.wait_group %0;\n" :: "n"(STAGES - 2));
            __syncthreads();
        }

        #pragma unroll
        for (int mt = 0; mt < 4; mt++) {
            #pragma unroll
            for (int nt = 0; nt < 8; nt++) {
                int row = bm + wr * 64 + mt * 16 + grp;
                int col = bn + wc * 64 + nt * 8 + tig * 2;
                *reinterpret_cast<float2*>(C + (size_t)row * ldc + col) =
                    make_float2(acc[mt][nt][0], acc[mt][nt][1]);
                *reinterpret_cast<float2*>(C + (size_t)(row + 8) * ldc + col) =
                    make_float2(acc[mt][nt][2], acc[mt][nt][3]);
            }
        }
        __syncthreads();
    }
#endif
}

// ---------------- per-token attention (RoPE + 8-way softmax) ----------------
__global__ void attn_kernel(const float* __restrict__ qkv,
                            const float* __restrict__ cos_g,
                            const float* __restrict__ sin_g,
                            float* __restrict__ attn_out) {
    const int t = blockIdx.x;
    const int s = t & (S_ - 1);
    const float* base = qkv + (size_t)t * 3072;

    __shared__ float2 ks2[KVH_][32];
    __shared__ float2 vs2[KVH_][32];

    const int tid = threadIdx.x;
    const int j = tid >> 5, i = tid & 31;

    {
        float2 kv = reinterpret_cast<const float2*>(base + 2048 + j * 64)[i];
        float c = cos_g[s * 32 + i], sn = sin_g[s * 32 + i];
        ks2[j][i] = make_float2(kv.x * c - kv.y * sn, kv.x * sn + kv.y * c);
        vs2[j][i] = reinterpret_cast<const float2*>(base + 2560 + j * 64)[i];
    }
    __syncthreads();

    const int warp = tid >> 5, lane = tid & 31;
    const float cc  = cos_g[s * 32 + lane];
    const float ssn = sin_g[s * 32 + lane];

    #pragma unroll
    for (int hh = 0; hh < 4; hh++) {
        int h = warp * 4 + hh;
        float2 q = reinterpret_cast<const float2*>(base + h * 64)[lane];
        float qr = q.x * cc - q.y * ssn;
        float qi = q.x * ssn + q.y * cc;

        float sc[KVH_];
        #pragma unroll
        for (int jj = 0; jj < KVH_; jj++) {
            float2 k2 = ks2[jj][lane];
            float p = qr * k2.x + qi * k2.y;
            p += __shfl_xor_sync(0xffffffffu, p, 16);
            p += __shfl_xor_sync(0xffffffffu, p, 8);
            p += __shfl_xor_sync(0xffffffffu, p, 4);
            p += __shfl_xor_sync(0xffffffffu, p, 2);
            p += __shfl_xor_sync(0xffffffffu, p, 1);
            sc[jj] = p * 0.125f;
        }
        float m = sc[0];
        #pragma unroll
        for (int jj = 1; jj < KVH_; jj++) m = fmaxf(m, sc[jj]);
        float sum = 0.f;
        #pragma unroll
        for (int jj = 0; jj < KVH_; jj++) { sc[jj] = __expf(sc[jj] - m); sum += sc[jj]; }
        float inv = 1.f / sum;
        float o0 = 0.f, o1 = 0.f;
        #pragma unroll
        for (int jj = 0; jj < KVH_; jj++) {
            float w = sc[jj] * inv;
            float2 v2 = vs2[jj][lane];
            o0 += w * v2.x;
            o1 += w * v2.y;
        }
        reinterpret_cast<float2*>(attn_out + (size_t)t * 2048 + h * 64)[lane] =
            make_float2(round_tf32f(o0), round_tf32f(o1));
    }
}

// ---------------- launch ----------------
extern "C" void kernel_launch(void* const* d_in, const int* in_sizes, int n_in,
                              void* d_out, int out_size) {
    const float* x  = (const float*)d_in[0];
    const float* wq = (const float*)d_in[1];
    const float* wk = (const float*)d_in[2];
    const float* wv = (const float*)d_in[3];
    const float* wo = (const float*)d_in[4];
    const float* fc = (const float*)d_in[5];
    const float* fs = (const float*)d_in[6];
    float* out = (float*)d_out;

    float *xr, *w, *qkv, *attn;
    cudaGetSymbolAddress((void**)&xr,   g_xr);
    cudaGetSymbolAddress((void**)&w,    g_w);
    cudaGetSymbolAddress((void**)&qkv,  g_qkv);
    cudaGetSymbolAddress((void**)&attn, g_attn);

    cudaFuncSetAttribute(gemm_tc, cudaFuncAttributeMaxDynamicSharedMemorySize, SMEM_REQ);

    auto launch_round = [](const float* src, float* dst, size_t n) {
        int n4 = (int)(n / 4);
        round_k<<<(n4 + 255) / 256, 256>>>((const float4*)src, (float4*)dst, n4);
    };
    launch_round(x,  xr,                       (size_t)NTOK * DIM_);
    launch_round(wq, w,                        (size_t)2048 * DIM_);
    launch_round(wk, w + (size_t)2048 * DIM_,  (size_t)512 * DIM_);
    launch_round(wv, w + (size_t)2560 * DIM_,  (size_t)512 * DIM_);
    launch_round(wo, w + WO_OFF,               (size_t)2048 * DIM_);

    // fused QKV projection: [8192,2048] x [3072,2048]^T -> [8192,3072]
    gemm_tc<<<dim3(3072 / 256, NTOK / 256), 256, SMEM_REQ>>>(xr, w, qkv, DIM_, 3072);

    // RoPE + per-token attention (tf32-rounded output)
    attn_kernel<<<NTOK, 256>>>(qkv, fc, fs, attn);

    // output projection: [8192,2048] x [2048,2048]^T -> [8192,2048]
    gemm_tc<<<dim3(DIM_ / 256, NTOK / 256), 256, SMEM_REQ>>>(attn, w + WO_OFF, out, DIM_, DIM_);
}

// round 6
// speedup vs baseline: 2.4975x; 1.2632x over previous
#include <cuda_runtime.h>
#include <cstdint>

// ---- detect architecture-specific (sm_103a/sm_100a) compilation pass ----
#ifndef HAS_TC
#  if defined(__CUDA_ARCH_FEAT_SM103_ALL) || defined(__CUDA_ARCH_FEAT_SM100_ALL)
#    define HAS_TC 1
#  endif
#endif
#ifndef HAS_TC
#  ifdef __CUDA_ARCH_HAS_FEATURE__
#    if __CUDA_ARCH_HAS_FEATURE__(SM103_ALL) || __CUDA_ARCH_HAS_FEATURE__(SM100_ALL)
#      define HAS_TC 1
#    endif
#  endif
#endif
#ifndef HAS_TC
#  define HAS_TC 0
#endif

#define NTOK  8192
#define DIM_  2048
#define S_    2048
#define KVH_  8

// ---------------- tile config ----------------
// tcgen05 path: one CTA computes 256x256 via two M=128 MMAs sharing B.
// Stage layout (64 KB): [A0 16KB | A1 16KB | B 32KB] x 3 stages.
// PREF=1: stage reuse at j=kt+1 depends on MMA(kt-2) -> 2 iterations of slack.
#define BK 32                      // floats per K step (128B rows)
#define STAGES 3
#define PREF 1
#define STAGE_BYTES 65536
#define A0_OFF 0
#define A1_OFF 16384
#define B_OFF  32768

#define SMEM_AOFF 1024
#define SMEM_REQ  (1024 + STAGES * STAGE_BYTES)   // 197632

#define TMEM_COLS 512
// cg1 idesc: c=F32, a=TF32, b=TF32, M=128, N=256, K-major both
#define IDESC ((1u << 4) | (2u << 7) | (2u << 10) | ((256 / 8) << 17) | ((128 / 16) << 24))

// ---------------- scratch ----------------
__device__ float g_xr  [(size_t)NTOK * DIM_];
__device__ float g_w   [(size_t)(3072 + 2048) * DIM_];
__device__ float g_qkv [(size_t)NTOK * 3072];
__device__ float g_attn[(size_t)NTOK * DIM_];
#define WO_OFF ((size_t)3072 * DIM_)

// ---------------- helpers ----------------
__device__ __forceinline__ uint32_t smem_u32(const void* p) {
    return (uint32_t)__cvta_generic_to_shared(p);
}
__device__ __forceinline__ void cp_async16(uint32_t saddr, const void* gptr) {
    asm volatile("cp.async.cg.shared.global [%0], [%1], 16;\n" :: "r"(saddr), "l"(gptr));
}
__device__ __forceinline__ uint32_t swz128(uint32_t off) {
    return off ^ ((off >> 3) & 0x70);
}
__device__ __forceinline__ float round_tf32f(float f) {
    uint32_t u;
    asm("cvt.rna.tf32.f32 %0, %1;" : "=r"(u) : "f"(f));
    return __uint_as_float(u);
}
__device__ __forceinline__ uint32_t lds32(const char* smem, uint32_t off) {
    return *reinterpret_cast<const uint32_t*>(smem + off);
}
__device__ __forceinline__ void mma_tf32(float c[4], const uint32_t a[4], const uint32_t b[2]) {
    asm volatile(
        "mma.sync.aligned.m16n8k8.row.col.f32.tf32.tf32.f32 "
        "{%0,%1,%2,%3}, {%4,%5,%6,%7}, {%8,%9}, {%0,%1,%2,%3};"
        : "+f"(c[0]), "+f"(c[1]), "+f"(c[2]), "+f"(c[3])
        : "r"(a[0]), "r"(a[1]), "r"(a[2]), "r"(a[3]), "r"(b[0]), "r"(b[1]));
}

#if HAS_TC
#define MBARRIER_INIT(addr, cnt) \
    asm volatile("mbarrier.init.shared.b64 [%0], %1;" :: "r"(addr), "r"(cnt) : "memory")

#define MBARRIER_WAIT_PARITY(addr, ph) do {                                        \
    uint32_t _m = (addr); uint32_t _p = (ph); uint32_t _d;                         \
    asm volatile("{\n\t.reg .pred p;\n\t"                                          \
        "mbarrier.try_wait.parity.acquire.cta.shared::cta.b64 p, [%1], %2;\n\t"    \
        "selp.b32 %0, 1, 0, p;\n\t}"                                               \
        : "=r"(_d) : "r"(_m), "r"(_p) : "memory");                                 \
    if (!_d) {                                                                     \
        asm volatile("{\n\t.reg .pred P1;\n\t"                                     \
        "WL_%=:\n\t"                                                               \
        "mbarrier.try_wait.parity.acquire.cta.shared::cta.b64 P1, [%0], %1, 0x989680;\n\t" \
        "@P1 bra.uni WD_%=;\n\t"                                                   \
        "bra.uni WL_%=;\n\t"                                                       \
        "WD_%=:\n\t}" :: "r"(_m), "r"(_p) : "memory");                             \
    }                                                                              \
} while (0)

#define TCGEN05_ALLOC(saddr, ncols) \
    asm volatile("tcgen05.alloc.cta_group::1.sync.aligned.shared::cta.b32 [%0], %1;" \
                 :: "r"((uint32_t)(saddr)), "r"((uint32_t)(ncols)) : "memory")
#define TCGEN05_RELINQ() \
    asm volatile("tcgen05.relinquish_alloc_permit.cta_group::1.sync.aligned;")
#define TCGEN05_DEALLOC(tmem, ncols) \
    asm volatile("tcgen05.dealloc.cta_group::1.sync.aligned.b32 %0, %1;" \
                 :: "r"(tmem), "r"((uint32_t)(ncols)))
#define TCGEN05_COMMIT(mbar) \
    asm volatile("tcgen05.commit.cta_group::1.mbarrier::arrive::one.shared::cluster.b64 [%0];" \
                 :: "r"((uint32_t)(mbar)) : "memory")
#define TCGEN05_FENCE_AFTER()  asm volatile("tcgen05.fence::after_thread_sync;" ::: "memory")
#define TCGEN05_FENCE_BEFORE() asm volatile("tcgen05.fence::before_thread_sync;" ::: "memory")
#define TCGEN05_WAIT_LD()      asm volatile("tcgen05.wait::ld.sync.aligned;" ::: "memory")
#define FENCE_PROXY_ASYNC()    asm volatile("fence.proxy.async.shared::cta;" ::: "memory")

#define TCGEN05_LD_X32(r, taddr) \
    asm volatile("tcgen05.ld.sync.aligned.32x32b.x32.b32 " \
        "{%0, %1, %2, %3, %4, %5, %6, %7, %8, %9, %10, %11, %12, %13, %14, %15, " \
        " %16, %17, %18, %19, %20, %21, %22, %23, %24, %25, %26, %27, %28, %29, %30, %31}, [%32];" \
        : "=r"((r)[0]), "=r"((r)[1]), "=r"((r)[2]), "=r"((r)[3]),      \
          "=r"((r)[4]), "=r"((r)[5]), "=r"((r)[6]), "=r"((r)[7]),      \
          "=r"((r)[8]), "=r"((r)[9]), "=r"((r)[10]), "=r"((r)[11]),    \
          "=r"((r)[12]), "=r"((r)[13]), "=r"((r)[14]), "=r"((r)[15]),  \
          "=r"((r)[16]), "=r"((r)[17]), "=r"((r)[18]), "=r"((r)[19]),  \
          "=r"((r)[20]), "=r"((r)[21]), "=r"((r)[22]), "=r"((r)[23]),  \
          "=r"((r)[24]), "=r"((r)[25]), "=r"((r)[26]), "=r"((r)[27]),  \
          "=r"((r)[28]), "=r"((r)[29]), "=r"((r)[30]), "=r"((r)[31])   \
        : "r"(taddr))

static constexpr uint64_t SMEM_DESC_BASE_SW128 =
    (uint64_t(2) << 61) | (uint64_t(1) << 46) | (uint64_t(64) << 32) | (uint64_t(1) << 16);
#define MAKE_SMEM_DESC(addr) (SMEM_DESC_BASE_SW128 | ((uint64_t)((addr) >> 4) & 0x3FFF))

__device__ __forceinline__ void mma_tf32_ss(uint32_t d_tmem, uint64_t a_desc,
                                            uint64_t b_desc, uint32_t idesc, bool acc) {
    uint32_t en = acc ? 1u : 0u;
    asm volatile(
        "{\n\t.reg .pred p;\n\t"
        "setp.ne.u32 p, %4, 0;\n\t"
        "tcgen05.mma.cta_group::1.kind::tf32 [%0], %1, %2, %3, {%5, %5, %5, %5}, p;\n\t}"
        :: "r"(d_tmem), "l"(a_desc), "l"(b_desc), "r"(idesc), "r"(en), "r"(0u)
        : "memory");
}
#endif  // HAS_TC

// ---------------- tf32 pre-rounding ----------------
__global__ void round_k(const float4* __restrict__ in, float4* __restrict__ out, int n4) {
    int i = blockIdx.x * blockDim.x + threadIdx.x;
    if (i < n4) {
        float4 v = in[i];
        v.x = round_tf32f(v.x); v.y = round_tf32f(v.y);
        v.z = round_tf32f(v.z); v.w = round_tf32f(v.w);
        out[i] = v;
    }
}

// round all 4 weight matrices in one launch (wq 2048, wk 512, wv 512, wo 2048 rows x 2048)
__global__ void round_w4(const float4* __restrict__ wq, const float4* __restrict__ wk,
                         const float4* __restrict__ wv, const float4* __restrict__ wo,
                         float4* __restrict__ out) {
    const int i = blockIdx.x * blockDim.x + threadIdx.x;   // float4 index
    const int Q4  = 2048 * 2048 / 4;   // 1048576
    const int K4  = 512 * 2048 / 4;    // 262144
    const float4* src;
    int idx;
    if (i < Q4)                { src = wq; idx = i; }
    else if (i < Q4 + K4)      { src = wk; idx = i - Q4; }
    else if (i < Q4 + 2 * K4)  { src = wv; idx = i - Q4 - K4; }
    else                       { src = wo; idx = i - Q4 - 2 * K4; }
    float4 v = src[idx];
    v.x = round_tf32f(v.x); v.y = round_tf32f(v.y);
    v.z = round_tf32f(v.z); v.w = round_tf32f(v.w);
    out[i] = v;
}

// ---------------- GEMM: C[M,ldc] = A[M,K] * B[N,K]^T ----------------
// grid = (N/256, M/256), block = 256. Operands must be tf32-pre-rounded.
// tcgen05 path: 256x256 tile = two M=128 MMA dispatches sharing one B operand.
__global__ void __launch_bounds__(256, 1)
gemm_tc(const float* __restrict__ A, const float* __restrict__ Bm,
        float* __restrict__ C, int K, int ldc) {
    extern __shared__ char smem[];
    const uint32_t sbase = smem_u32(smem);
    const int tid = threadIdx.x;
    const int wid = tid >> 5, lid = tid & 31;
    const int bmp = blockIdx.y * 256;
    const int bn  = blockIdx.x * 256;
    const int KT = K / BK;

    const int r0 = tid >> 3;            // 0..31
    const int cb = (tid & 7) * 16;      // byte col within 128B row

#if HAS_TC
    // ======== tcgen05 path ========
    const float* A0g = A  + (size_t)bmp * K;
    const float* A1g = A  + (size_t)(bmp + 128) * K;
    const float* Bg0 = Bm + (size_t)bn * K;

    auto issue_loads = [&](int j) {
        const int s = j % STAGES;
        const uint32_t st = sbase + SMEM_AOFF + s * STAGE_BYTES;
        const size_t kof = (size_t)j * BK + (cb >> 2);
        #pragma unroll
        for (int r = 0; r < 128; r += 32) {
            int row = r + r0;
            uint32_t so = swz128(row * 128 + cb);
            cp_async16(st + A0_OFF + so, A0g + (size_t)row * K + kof);
            cp_async16(st + A1_OFF + so, A1g + (size_t)row * K + kof);
        }
        #pragma unroll
        for (int r = 0; r < 256; r += 32) {
            int row = r + r0;
            cp_async16(st + B_OFF + swz128(row * 128 + cb), Bg0 + (size_t)row * K + kof);
        }
    };

    const uint32_t EMPTY_BAR = sbase + 16;       // STAGES bars
    const uint32_t DONE_BAR  = sbase + 16 + STAGES * 8;

    if (wid == 0) TCGEN05_ALLOC(sbase, TMEM_COLS);
    if (tid == 0) {
        #pragma unroll
        for (int s = 0; s < STAGES; s++) MBARRIER_INIT(EMPTY_BAR + s * 8, 1);
        MBARRIER_INIT(DONE_BAR, 1);
    }
    __syncthreads();
    if (wid == 0) TCGEN05_RELINQ();

    uint32_t tmem;
    asm volatile("ld.shared.b32 %0, [%1];" : "=r"(tmem) : "r"(sbase));
    const uint32_t D0 = tmem, D1 = tmem + 256;

    #pragma unroll
    for (int j = 0; j < PREF; j++) {
        issue_loads(j);
        asm volatile("cp.async.commit_group;\n" ::);
    }

    for (int kt = 0; kt < KT; kt++) {
        const int j = kt + PREF;
        if (j < KT) {
            if (j >= STAGES) {
                int ph = ((j / STAGES) - 1) & 1;
                MBARRIER_WAIT_PARITY(EMPTY_BAR + (j % STAGES) * 8, ph);
            }
            issue_loads(j);
        }
        asm volatile("cp.async.commit_group;\n" ::);
        asm volatile("cp.async.wait_group %0;\n" :: "n"(PREF));
        FENCE_PROXY_ASYNC();
        __syncthreads();

        if (tid == 0) {
            const int s = kt % STAGES;
            const uint32_t st = sbase + SMEM_AOFF + s * STAGE_BYTES;
            uint64_t a0 = MAKE_SMEM_DESC(st + A0_OFF);
            uint64_t a1 = MAKE_SMEM_DESC(st + A1_OFF);
            uint64_t bd = MAKE_SMEM_DESC(st + B_OFF);
            bool acc0 = (kt > 0);
            #pragma unroll
            for (int k = 0; k < 4; k++) {
                mma_tf32_ss(D0, a0 + k * 2, bd + k * 2, IDESC, acc0 || (k > 0));
                mma_tf32_ss(D1, a1 + k * 2, bd + k * 2, IDESC, acc0 || (k > 0));
            }
            TCGEN05_COMMIT(EMPTY_BAR + s * 8);
        }
    }

    if (tid == 0) TCGEN05_COMMIT(DONE_BAR);
    MBARRIER_WAIT_PARITY(DONE_BAR, 0);
    TCGEN05_FENCE_AFTER();

    // epilogue: warps 0-3 -> D0 (rows bmp+0..127), warps 4-7 -> D1 (rows +128)
    {
        const int row = bmp + (wid >> 2) * 128 + (wid & 3) * 32 + lid;
        const uint32_t dT = (wid >> 2) ? D1 : D0;
        float* crow = C + (size_t)row * ldc + bn;
        #pragma unroll
        for (int c2 = 0; c2 < 256; c2 += 32) {
            uint32_t r[32];
            TCGEN05_LD_X32(r, dT + c2);
            TCGEN05_WAIT_LD();
            #pragma unroll
            for (int q = 0; q < 32; q += 4) {
                float4 v = make_float4(__uint_as_float(r[q]), __uint_as_float(r[q + 1]),
                                       __uint_as_float(r[q + 2]), __uint_as_float(r[q + 3]));
                *reinterpret_cast<float4*>(crow + c2 + q) = v;
            }
        }
    }
    TCGEN05_FENCE_BEFORE();
    __syncthreads();
    if (wid == 0) TCGEN05_DEALLOC(tmem, TMEM_COLS);

#else
    // ======== legacy mma.sync fallback: 256x256 tile in two sequential halves ========
    const int wr = wid >> 2, wc = wid & 3;
    const int grp = lid >> 2, tig = lid & 3;

    for (int half = 0; half < 2; half++) {
        const int bm = bmp + half * 128;

        auto issue_loads = [&](int j) {
            const int s = j % STAGES;
            const uint32_t st = sbase + SMEM_AOFF + s * STAGE_BYTES;
            const float* Ag = A  + (size_t)bm * K + (size_t)j * BK;
            const float* Bg = Bm + (size_t)bn * K + (size_t)j * BK;
            #pragma unroll
            for (int r = 0; r < 128; r += 32) {
                int row = r + r0;
                cp_async16(st + A0_OFF + swz128(row * 128 + cb), Ag + (size_t)row * K + (cb >> 2));
            }
            #pragma unroll
            for (int r = 0; r < 256; r += 32) {
                int row = r + r0;
                cp_async16(st + B_OFF + swz128(row * 128 + cb), Bg + (size_t)row * K + (cb >> 2));
            }
        };

        float acc[4][8][4];
        #pragma unroll
        for (int i = 0; i < 4; i++)
            #pragma unroll
            for (int j2 = 0; j2 < 8; j2++)
                #pragma unroll
                for (int r = 0; r < 4; r++) acc[i][j2][r] = 0.f;

        auto compute = [&](int s) {
            const char* st = smem + SMEM_AOFF + s * STAGE_BYTES;
            const char* as = st + A0_OFF;
            const char* bs = st + B_OFF;
            #pragma unroll
            for (int kk = 0; kk < BK; kk += 8) {
                uint32_t af[4][4], bf[8][2];
                #pragma unroll
                for (int mt = 0; mt < 4; mt++) {
                    int rb = wr * 64 + mt * 16;
                    af[mt][0] = lds32(as, swz128((rb + grp)     * 128 + (kk + tig) * 4));
                    af[mt][1] = lds32(as, swz128((rb + grp + 8) * 128 + (kk + tig) * 4));
                    af[mt][2] = lds32(as, swz128((rb + grp)     * 128 + (kk + tig + 4) * 4));
                    af[mt][3] = lds32(as, swz128((rb + grp + 8) * 128 + (kk + tig + 4) * 4));
                }
                #pragma unroll
                for (int nt = 0; nt < 8; nt++) {
                    int cbn = wc * 64 + nt * 8;
                    bf[nt][0] = lds32(bs, swz128((cbn + grp) * 128 + (kk + tig) * 4));
                    bf[nt][1] = lds32(bs, swz128((cbn + grp) * 128 + (kk + tig + 4) * 4));
                }
                #pragma unroll
                for (int mt = 0; mt < 4; mt++)
                    #pragma unroll
                    for (int nt = 0; nt < 8; nt++)
                        mma_tf32(acc[mt][nt], af[mt], bf[nt]);
            }
        };

        #pragma unroll
        for (int j = 0; j < STAGES - 1; j++) {
            issue_loads(j);
            asm volatile("cp.async.commit_group;\n" ::);
        }
        asm volatile("cp.async.wait_group %0;\n" :: "n"(STAGES - 2));
        __syncthreads();

        for (int kt = 0; kt < KT; kt++) {
            int j = kt + STAGES - 1;
            if (j < KT) issue_loads(j);
            asm volatile("cp.async.commit_group;\n" ::);
            compute(kt % STAGES);
            asm volatile("cp.async.wait_group %0;\n" :: "n"(STAGES - 2));
            __syncthreads();
        }

        #pragma unroll
        for (int mt = 0; mt < 4; mt++) {
            #pragma unroll
            for (int nt = 0; nt < 8; nt++) {
                int row = bm + wr * 64 + mt * 16 + grp;
                int col = bn + wc * 64 + nt * 8 + tig * 2;
                *reinterpret_cast<float2*>(C + (size_t)row * ldc + col) =
                    make_float2(acc[mt][nt][0], acc[mt][nt][1]);
                *reinterpret_cast<float2*>(C + (size_t)(row + 8) * ldc + col) =
                    make_float2(acc[mt][nt][2], acc[mt][nt][3]);
            }
        }
        __syncthreads();
    }
#endif
}

// ---------------- per-token attention (RoPE + 8-way softmax) ----------------
__global__ void attn_kernel(const float* __restrict__ qkv,
                            const float* __restrict__ cos_g,
                            const float* __restrict__ sin_g,
                            float* __restrict__ attn_out) {
    const int t = blockIdx.x;
    const int s = t & (S_ - 1);
    const float* base = qkv + (size_t)t * 3072;

    __shared__ float2 ks2[KVH_][32];
    __shared__ float2 vs2[KVH_][32];

    const int tid = threadIdx.x;
    const int j = tid >> 5, i = tid & 31;

    {
        float2 kv = reinterpret_cast<const float2*>(base + 2048 + j * 64)[i];
        float c = cos_g[s * 32 + i], sn = sin_g[s * 32 + i];
        ks2[j][i] = make_float2(kv.x * c - kv.y * sn, kv.x * sn + kv.y * c);
        vs2[j][i] = reinterpret_cast<const float2*>(base + 2560 + j * 64)[i];
    }
    __syncthreads();

    const int warp = tid >> 5, lane = tid & 31;
    const float cc  = cos_g[s * 32 + lane];
    const float ssn = sin_g[s * 32 + lane];

    #pragma unroll
    for (int hh = 0; hh < 4; hh++) {
        int h = warp * 4 + hh;
        float2 q = reinterpret_cast<const float2*>(base + h * 64)[lane];
        float qr = q.x * cc - q.y * ssn;
        float qi = q.x * ssn + q.y * cc;

        float sc[KVH_];
        #pragma unroll
        for (int jj = 0; jj < KVH_; jj++) {
            float2 k2 = ks2[jj][lane];
            float p = qr * k2.x + qi * k2.y;
            p += __shfl_xor_sync(0xffffffffu, p, 16);
            p += __shfl_xor_sync(0xffffffffu, p, 8);
            p += __shfl_xor_sync(0xffffffffu, p, 4);
            p += __shfl_xor_sync(0xffffffffu, p, 2);
            p += __shfl_xor_sync(0xffffffffu, p, 1);
            sc[jj] = p * 0.125f;
        }
        float m = sc[0];
        #pragma unroll
        for (int jj = 1; jj < KVH_; jj++) m = fmaxf(m, sc[jj]);
        float sum = 0.f;
        #pragma unroll
        for (int jj = 0; jj < KVH_; jj++) { sc[jj] = __expf(sc[jj] - m); sum += sc[jj]; }
        float inv = 1.f / sum;
        float o0 = 0.f, o1 = 0.f;
        #pragma unroll
        for (int jj = 0; jj < KVH_; jj++) {
            float w = sc[jj] * inv;
            float2 v2 = vs2[jj][lane];
            o0 += w * v2.x;
            o1 += w * v2.y;
        }
        reinterpret_cast<float2*>(attn_out + (size_t)t * 2048 + h * 64)[lane] =
            make_float2(round_tf32f(o0), round_tf32f(o1));
    }
}

// ---------------- launch ----------------
extern "C" void kernel_launch(void* const* d_in, const int* in_sizes, int n_in,
                              void* d_out, int out_size) {
    const float* x  = (const float*)d_in[0];
    const float* wq = (const float*)d_in[1];
    const float* wk = (const float*)d_in[2];
    const float* wv = (const float*)d_in[3];
    const float* wo = (const float*)d_in[4];
    const float* fc = (const float*)d_in[5];
    const float* fs = (const float*)d_in[6];
    float* out = (float*)d_out;

    float *xr, *w, *qkv, *attn;
    cudaGetSymbolAddress((void**)&xr,   g_xr);
    cudaGetSymbolAddress((void**)&w,    g_w);
    cudaGetSymbolAddress((void**)&qkv,  g_qkv);
    cudaGetSymbolAddress((void**)&attn, g_attn);

    cudaFuncSetAttribute(gemm_tc, cudaFuncAttributeMaxDynamicSharedMemorySize, SMEM_REQ);

    // pre-round all GEMM operands to tf32 (RNA) so HW truncation is lossless
    {
        int n4 = (int)((size_t)NTOK * DIM_ / 4);
        round_k<<<(n4 + 255) / 256, 256>>>((const float4*)x, (float4*)xr, n4);
        int w4 = (int)((size_t)(3072 + 2048) * DIM_ / 4);
        round_w4<<<(w4 + 255) / 256, 256>>>((const float4*)wq, (const float4*)wk,
                                            (const float4*)wv, (const float4*)wo,
                                            (float4*)w);
    }

    // fused QKV projection: [8192,2048] x [3072,2048]^T -> [8192,3072]
    gemm_tc<<<dim3(3072 / 256, NTOK / 256), 256, SMEM_REQ>>>(xr, w, qkv, DIM_, 3072);

    // RoPE + per-token attention (tf32-rounded output)
    attn_kernel<<<NTOK, 256>>>(qkv, fc, fs, attn);

    // output projection: [8192,2048] x [2048,2048]^T -> [8192,2048]
    gemm_tc<<<dim3(DIM_ / 256, NTOK / 256), 256, SMEM_REQ>>>(attn, w + WO_OFF, out, DIM_, DIM_);
}